// round 15
// baseline (speedup 1.0000x reference)
#include <cuda_runtime.h>
#include <cuda_fp16.h>
#include <cstdint>

#define DIM     1024
#define BATCH   16384
#define NLAYERS 18

// ---------------- GEMM tiling: CTA 128x128, 4 warps, warp tile 64x64 ----------------
#define BM 128
#define BN 128
#define BK 32                     // fp16 per K-chunk = 64B per row
#define NCHUNK (DIM / BK)         // 32
#define NTHREADS 128

// smem stage: X 128x64B = 8KB, W 128x64B = 8KB -> stage 16KB, 2 stages = 32KB/CTA
#define OFF_W  8192u
#define STAGE  16384u
#define SM_TOTAL (2 * 16384)

// ---------------- static device scratch ----------------
__device__ __align__(16) __half g_W  [NLAYERS * DIM * DIM];
__device__ __align__(16) __half g_A0 [BATCH * DIM];
__device__ __align__(16) __half g_A1 [BATCH * DIM];
__device__ __align__(16) __half g_R  [BATCH * DIM];

// ---------------- PTX helpers ----------------
__device__ __forceinline__ uint32_t smem_u32(const void* p) {
    uint32_t a;
    asm("{ .reg .u64 t; cvta.to.shared.u64 t, %1; cvt.u32.u64 %0, t; }" : "=r"(a) : "l"(p));
    return a;
}
#define CP_ASYNC16(dst, src) \
    asm volatile("cp.async.cg.shared.global [%0], [%1], 16;\n" :: "r"(dst), "l"(src))
#define CP_COMMIT() asm volatile("cp.async.commit_group;\n" ::: "memory")
#define CP_WAIT1()  asm volatile("cp.async.wait_group 1;\n" ::: "memory")
#define CP_WAIT0()  asm volatile("cp.async.wait_group 0;\n" ::: "memory")

#define LDSM_X4(r0, r1, r2, r3, addr) \
    asm volatile("ldmatrix.sync.aligned.m8n8.x4.shared.b16 {%0,%1,%2,%3}, [%4];\n" \
                 : "=r"(r0), "=r"(r1), "=r"(r2), "=r"(r3) : "r"(addr))

#define MMA4(d, a0, a1, a2, a3, b0, b1) \
    asm volatile("mma.sync.aligned.m16n8k16.row.col.f32.f16.f16.f32 " \
                 "{%0,%1,%2,%3},{%4,%5,%6,%7},{%8,%9},{%0,%1,%2,%3};\n" \
                 : "+f"((d)[0]), "+f"((d)[1]), "+f"((d)[2]), "+f"((d)[3]) \
                 : "r"(a0), "r"(a1), "r"(a2), "r"(a3), "r"(b0), "r"(b1))

// packed f32x2 helpers (k_prep inner loop; proven R11)
#define PACK2(u, lo, hi) \
    asm volatile("mov.b64 %0, {%1, %2};\n" : "=l"(u) : "f"(lo), "f"(hi))
#define UNPACK2(lo, hi, u) \
    asm volatile("mov.b64 {%0, %1}, %2;\n" : "=f"(lo), "=f"(hi) : "l"(u))
#define FMA2(a, b, c) \
    asm volatile("fma.rn.f32x2 %0, %1, %2, %0;\n" : "+l"(a) : "l"(b), "l"(c))

// swizzle for 64B rows: 16B-group g XOR (row & 3) — verified conflict-free (R6..R14)
__device__ __forceinline__ uint32_t swz64(uint32_t row, uint32_t g16) {
    return row * 64u + ((g16 ^ (row & 3u)) << 4);
}

// stage loader: 16KB / 128 threads = 8 cp.async x16B per thread
__device__ __forceinline__ void load_chunk(
    uint32_t st, int c, int tid, const char* pX, const char* pW)
{
    const size_t koff = (size_t)c * 64u;
#pragma unroll
    for (int i = 0; i < 8; i++) {
        int idx = tid + i * NTHREADS;     // 0..1023
        int arr = idx >> 9;               // 0: X, 1: W
        int r   = (idx >> 2) & 127;       // row 0..127
        int g   = idx & 3;                // 16B group 0..3
        const char* base = arr ? pW : pX;
        uint32_t dst = st + (uint32_t)arr * OFF_W + swz64((uint32_t)r, (uint32_t)g);
        CP_ASYNC16(dst, base + (size_t)r * 2048 + koff + (size_t)(g * 16));
    }
    CP_COMMIT();
}

// ---------------- fused GEMM layer: fp16 x fp16, fp32 accum, warp tile 64x64 ----------------
// MODE 0: relu(C+bias)->fp16 | MODE 1: C+bias+res->fp16 | MODE 2: C+bias+res->fp32
template<int MODE>
__global__ void __launch_bounds__(NTHREADS, 2)
k_gemm(const __half* __restrict__ X, const __half* __restrict__ W,
       const float* __restrict__ bias,
       __half* __restrict__ O,
       const __half* __restrict__ R,
       float* __restrict__ Of)
{
    extern __shared__ char smem[];
    const uint32_t sb = smem_u32(smem);
    const int tid = threadIdx.x, wid = tid >> 5, lane = tid & 31;
    const int Mb = blockIdx.y * BM, Nb = blockIdx.x * BN;
    const int wm = (wid & 1) * 64;          // 2 m-warps
    const int wn = (wid >> 1) * 64;         // 2 n-warps

    const char* pX = (const char*)(X + (size_t)Mb * DIM);
    const char* pW = (const char*)(W + (size_t)Nb * DIM);

    const int l7  = lane & 7;
    const int l15 = lane & 15;
    const int lhi = lane >> 4;              // 0/1
    const int lb8 = ((lane >> 3) & 1) << 3;

    uint32_t adA[2][4], adB[2][4];
#pragma unroll
    for (int kk = 0; kk < 2; kk++) {
#pragma unroll
        for (int mi = 0; mi < 4; mi++) {
            uint32_t r = (uint32_t)(wm + mi * 16 + l15);
            adA[kk][mi] = swz64(r, (uint32_t)(2 * kk + lhi));
        }
#pragma unroll
        for (int j = 0; j < 4; j++) {
            uint32_t r = (uint32_t)(wn + j * 16 + l7 + lb8);
            adB[kk][j] = swz64(r, (uint32_t)(2 * kk + lhi));
        }
    }

    float acc[4][8][4];
#pragma unroll
    for (int mi = 0; mi < 4; mi++)
#pragma unroll
        for (int ni = 0; ni < 8; ni++)
#pragma unroll
            for (int k = 0; k < 4; k++) acc[mi][ni][k] = 0.f;

    load_chunk(sb, 0, tid, pX, pW);

#pragma unroll 1
    for (int c = 0; c < NCHUNK; c++) {
        const uint32_t st = sb + (uint32_t)(c & 1) * STAGE;
        if (c + 1 < NCHUNK) {
            load_chunk(sb + (uint32_t)((c + 1) & 1) * STAGE, c + 1, tid, pX, pW);
            CP_WAIT1();
        } else {
            CP_WAIT0();
        }
        __syncthreads();

        const uint32_t stX = st, stW = st + OFF_W;
#pragma unroll
        for (int kk = 0; kk < 2; kk++) {
            uint32_t aF[4][4], bF[4][4];
#pragma unroll
            for (int mi = 0; mi < 4; mi++)
                LDSM_X4(aF[mi][0], aF[mi][1], aF[mi][2], aF[mi][3], stX + adA[kk][mi]);
#pragma unroll
            for (int j = 0; j < 4; j++)
                LDSM_X4(bF[j][0], bF[j][1], bF[j][2], bF[j][3], stW + adB[kk][j]);
#pragma unroll
            for (int mi = 0; mi < 4; mi++)
#pragma unroll
                for (int j = 0; j < 4; j++) {
                    MMA4(acc[mi][2 * j],     aF[mi][0], aF[mi][1], aF[mi][2], aF[mi][3], bF[j][0], bF[j][2]);
                    MMA4(acc[mi][2 * j + 1], aF[mi][0], aF[mi][1], aF[mi][2], aF[mi][3], bF[j][1], bF[j][3]);
                }
        }
        __syncthreads();
    }

    // ---- epilogue ----
    auto emit = [&](int r, int c, float v0, float v1) {
        size_t off = (size_t)r * DIM + c;
        if (MODE >= 1) {
            __half2 r2 = *reinterpret_cast<const __half2*>(R + off);
            v0 += __half2float(r2.x);
            v1 += __half2float(r2.y);
        }
        if (MODE == 0) { v0 = fmaxf(v0, 0.f); v1 = fmaxf(v1, 0.f); }
        if (MODE == 2) {
            *reinterpret_cast<float2*>(Of + off) = make_float2(v0, v1);
        } else {
            __half2 h2; h2.x = __float2half(v0); h2.y = __float2half(v1);
            *reinterpret_cast<__half2*>(O + off) = h2;
        }
    };

    const int g  = lane >> 2;
    const int tg = lane & 3;
#pragma unroll
    for (int mi = 0; mi < 4; mi++) {
#pragma unroll
        for (int ni = 0; ni < 8; ni++) {
            int r0 = Mb + wm + mi * 16 + g;
            int c0 = Nb + wn + ni * 8 + tg * 2;
            float b0 = __ldg(bias + c0), b1 = __ldg(bias + c0 + 1);
            emit(r0,     c0, acc[mi][ni][0] + b0, acc[mi][ni][1] + b1);
            emit(r0 + 8, c0, acc[mi][ni][2] + b0, acc[mi][ni][3] + b1);
        }
    }
}

// ---------------- split input x -> fp16 in R ----------------
__global__ void k_split(const float* __restrict__ x, __half* __restrict__ r) {
    int i4 = blockIdx.x * blockDim.x + threadIdx.x;
    float4 v = reinterpret_cast<const float4*>(x)[i4];
    __half2 h0; h0.x = __float2half(v.x); h0.y = __float2half(v.y);
    __half2 h1; h1.x = __float2half(v.z); h1.y = __float2half(v.w);
    __half2* R2 = reinterpret_cast<__half2*>(r);
    R2[i4 * 2]     = h0;
    R2[i4 * 2 + 1] = h1;
}

// ---------------- dequant + fold LoRA -> fp16 W (2 outputs/thread; R11 core) ----------------
__global__ void __launch_bounds__(256)
k_prep(const int* __restrict__ qw, const float* __restrict__ scale,
       const float* __restrict__ la, const float* __restrict__ lb) {
    int idx2 = blockIdx.x * 256 + threadIdx.x;        // < 18*1024*512
    int l    = idx2 >> 19;
    int rem  = idx2 & 0x7FFFF;
    int o    = rem >> 9;
    int i    = (rem & 511) * 2;

    size_t base = ((size_t)l << 20) + ((size_t)o << 10) + (size_t)i;
    int2 q2 = *reinterpret_cast<const int2*>(qw + base);
    float s = scale[(l << 16) + (o << 6) + (i >> 4)];
    float w0 = ((float)q2.x / 15.0f * 2.0f - 1.0f) * s;
    float w1 = ((float)q2.y / 15.0f * 2.0f - 1.0f) * s;

    const float4* lb4 = reinterpret_cast<const float4*>(lb + l * (DIM * 32) + o * 32);
    float lbv[32];
#pragma unroll
    for (int q = 0; q < 8; q++) {
        float4 v = lb4[q];
        lbv[q * 4]     = v.x; lbv[q * 4 + 1] = v.y;
        lbv[q * 4 + 2] = v.z; lbv[q * 4 + 3] = v.w;
    }

    const float* lar = la + l * (32 * DIM) + i;
    unsigned long long accp;
    PACK2(accp, w0, w1);
#pragma unroll
    for (int r = 0; r < 32; r++) {
        float2 a2 = *reinterpret_cast<const float2*>(lar + (size_t)r * DIM);
        unsigned long long ap, bp;
        PACK2(ap, a2.x, a2.y);
        PACK2(bp, lbv[r], lbv[r]);
        FMA2(accp, bp, ap);
    }
    float r0, r1;
    UNPACK2(r0, r1, accp);

    __half2 h2; h2.x = __float2half(r0); h2.y = __float2half(r1);
    *reinterpret_cast<__half2*>(g_W + base) = h2;
}

// ---------------- LayerNorm (fp16 in/out, vectorized) ----------------
__device__ __forceinline__ float blockSum256(float v, float* red) {
#pragma unroll
    for (int o = 16; o > 0; o >>= 1) v += __shfl_xor_sync(0xffffffffu, v, o);
    int w = threadIdx.x >> 5;
    if ((threadIdx.x & 31) == 0) red[w] = v;
    __syncthreads();
    float t = 0.f;
#pragma unroll
    for (int i = 0; i < 8; i++) t += red[i];
    __syncthreads();
    return t;
}

__global__ void k_ln(const __half* __restrict__ I,
                     const float* __restrict__ gw, const float* __restrict__ gb,
                     __half* __restrict__ O)
{
    __shared__ float red[8];
    const int row = blockIdx.x;
    const int tid = threadIdx.x;
    const size_t base = (size_t)row * DIM;
    const int c0 = tid * 4;

    uint2 iv = *reinterpret_cast<const uint2*>(I + base + c0);
    const __half2* ip = reinterpret_cast<const __half2*>(&iv);
    float x[4];
    x[0] = __half2float(ip[0].x);
    x[1] = __half2float(ip[0].y);
    x[2] = __half2float(ip[1].x);
    x[3] = __half2float(ip[1].y);

    float s = x[0] + x[1] + x[2] + x[3];
    float mu = blockSum256(s, red) * (1.0f / DIM);
    float d[4], s2 = 0.f;
#pragma unroll
    for (int j = 0; j < 4; j++) { d[j] = x[j] - mu; s2 += d[j] * d[j]; }
    float var = blockSum256(s2, red) * (1.0f / DIM);
    float inv = rsqrtf(var + 1e-5f);

    float4 gwv = *reinterpret_cast<const float4*>(gw + c0);
    float4 gbv = *reinterpret_cast<const float4*>(gb + c0);
    float y0 = d[0] * inv * gwv.x + gbv.x;
    float y1 = d[1] * inv * gwv.y + gbv.y;
    float y2 = d[2] * inv * gwv.z + gbv.z;
    float y3 = d[3] * inv * gwv.w + gbv.w;

    uint2 ov;
    __half2* op = reinterpret_cast<__half2*>(&ov);
    op[0].x = __float2half(y0); op[0].y = __float2half(y1);
    op[1].x = __float2half(y2); op[1].y = __float2half(y3);
    *reinterpret_cast<uint2*>(O + base + c0) = ov;
}

// ---------------- orchestration: 3-buffer rotation (R, A0, A1) ----------------
extern "C" void kernel_launch(void* const* d_in, const int* in_sizes, int n_in,
                              void* d_out, int out_size) {
    (void)in_sizes; (void)n_in; (void)out_size;
    const float* x     = (const float*)d_in[0];
    const float* scale = (const float*)d_in[1];
    const float* bias  = (const float*)d_in[2];
    const float* la    = (const float*)d_in[3];
    const float* lb    = (const float*)d_in[4];
    const float* lnw   = (const float*)d_in[5];
    const float* lnb   = (const float*)d_in[6];
    const int*   qw    = (const int*)d_in[7];

    __half *W, *A0, *A1, *R;
    cudaGetSymbolAddress((void**)&W,  g_W);
    cudaGetSymbolAddress((void**)&A0, g_A0);
    cudaGetSymbolAddress((void**)&A1, g_A1);
    cudaGetSymbolAddress((void**)&R,  g_R);

    cudaFuncSetAttribute(k_gemm<0>, cudaFuncAttributeMaxDynamicSharedMemorySize, SM_TOTAL);
    cudaFuncSetAttribute(k_gemm<1>, cudaFuncAttributeMaxDynamicSharedMemorySize, SM_TOTAL);
    cudaFuncSetAttribute(k_gemm<2>, cudaFuncAttributeMaxDynamicSharedMemorySize, SM_TOTAL);

    k_split<<<BATCH * DIM / 4 / 256, 256>>>(x, R);
    k_prep <<<NLAYERS * DIM * DIM / 2 / 256, 256>>>(qw, scale, la, lb);

    dim3 ggrid(DIM / BN, BATCH / BM);   // (8, 128)
    int li = 0;
    for (int blk = 0; blk < 6; ++blk) {
        // g0: R -> A0 (relu)
        const int W0 = li * DIM * DIM;
        k_gemm<0><<<ggrid, NTHREADS, SM_TOTAL>>>(R, W + W0, bias + li * DIM, A0, nullptr, nullptr);
        li++;
        // g1: A0 -> A1 (relu)
        const int W1 = li * DIM * DIM;
        k_gemm<0><<<ggrid, NTHREADS, SM_TOTAL>>>(A0, W + W1, bias + li * DIM, A1, nullptr, nullptr);
        li++;
        // g2: A1 + R(residual) -> A0  (or d_out for last block)
        const int W2 = li * DIM * DIM;
        if (blk < 5) {
            k_gemm<1><<<ggrid, NTHREADS, SM_TOTAL>>>(A1, W + W2, bias + li * DIM, A0, R, nullptr);
            li++;
            // LN: A0 -> R  (R doubles as next block's input AND residual)
            k_ln<<<BATCH, 256>>>(A0, lnw + blk * DIM, lnb + blk * DIM, R);
        } else {
            k_gemm<2><<<ggrid, NTHREADS, SM_TOTAL>>>(A1, W + W2, bias + li * DIM,
                                                     nullptr, R, (float*)d_out);
            li++;
        }
    }
}

// round 16
// speedup vs baseline: 1.8236x; 1.8236x over previous
#include <cuda_runtime.h>
#include <cuda_fp16.h>
#include <cstdint>

#define DIM     1024
#define BATCH   16384
#define NLAYERS 18

// ---------------- GEMM tiling: CTA 128x128, 8 warps, warp tile 64x32, BK=64 ----------------
#define BM 128
#define BN 128
#define BK 64                     // fp16 per K-chunk = 128B per row
#define NCHUNK (DIM / BK)         // 16
#define NTHREADS 256

// smem stage: X 128x128B = 16KB, W 128x128B = 16KB -> stage 32KB, 2 stages = 64KB/CTA
#define OFF_W  16384u
#define STAGE  32768u
#define SM_TOTAL (2 * 32768)

// ---------------- static device scratch ----------------
__device__ __align__(16) __half g_W  [NLAYERS * DIM * DIM];
__device__ __align__(16) __half g_A0 [BATCH * DIM];
__device__ __align__(16) __half g_A1 [BATCH * DIM];
__device__ __align__(16) __half g_R  [BATCH * DIM];

// ---------------- PTX helpers ----------------
__device__ __forceinline__ uint32_t smem_u32(const void* p) {
    uint32_t a;
    asm("{ .reg .u64 t; cvta.to.shared.u64 t, %1; cvt.u32.u64 %0, t; }" : "=r"(a) : "l"(p));
    return a;
}
#define CP_ASYNC16(dst, src) \
    asm volatile("cp.async.cg.shared.global [%0], [%1], 16;\n" :: "r"(dst), "l"(src))
#define CP_COMMIT() asm volatile("cp.async.commit_group;\n" ::: "memory")
#define CP_WAIT1()  asm volatile("cp.async.wait_group 1;\n" ::: "memory")
#define CP_WAIT0()  asm volatile("cp.async.wait_group 0;\n" ::: "memory")

#define LDSM_X4(r0, r1, r2, r3, addr) \
    asm volatile("ldmatrix.sync.aligned.m8n8.x4.shared.b16 {%0,%1,%2,%3}, [%4];\n" \
                 : "=r"(r0), "=r"(r1), "=r"(r2), "=r"(r3) : "r"(addr))

#define MMA4(d, a0, a1, a2, a3, b0, b1) \
    asm volatile("mma.sync.aligned.m16n8k16.row.col.f32.f16.f16.f32 " \
                 "{%0,%1,%2,%3},{%4,%5,%6,%7},{%8,%9},{%0,%1,%2,%3};\n" \
                 : "+f"((d)[0]), "+f"((d)[1]), "+f"((d)[2]), "+f"((d)[3]) \
                 : "r"(a0), "r"(a1), "r"(a2), "r"(a3), "r"(b0), "r"(b1))

// packed f32x2 helpers (k_prep inner loop; proven R11)
#define PACK2(u, lo, hi) \
    asm volatile("mov.b64 %0, {%1, %2};\n" : "=l"(u) : "f"(lo), "f"(hi))
#define UNPACK2(lo, hi, u) \
    asm volatile("mov.b64 {%0, %1}, %2;\n" : "=f"(lo), "=f"(hi) : "l"(u))
#define FMA2(a, b, c) \
    asm volatile("fma.rn.f32x2 %0, %1, %2, %0;\n" : "+l"(a) : "l"(b), "l"(c))

// swizzle for 128B rows: 16B-group g XOR (row & 7)
__device__ __forceinline__ uint32_t swz128(uint32_t row, uint32_t g16) {
    return row * 128u + ((g16 ^ (row & 7u)) << 4);
}

// stage loader: 32KB / 256 threads = 8 cp.async x16B per thread
__device__ __forceinline__ void load_chunk(
    uint32_t st, int c, int tid, const char* pX, const char* pW)
{
    const size_t koff = (size_t)c * 128u;
#pragma unroll
    for (int i = 0; i < 8; i++) {
        int idx = tid + i * NTHREADS;     // 0..2047
        int arr = idx >> 10;              // 0: X, 1: W
        int r   = (idx >> 3) & 127;       // row 0..127
        int g   = idx & 7;                // 16B group 0..7
        const char* base = arr ? pW : pX;
        uint32_t dst = st + (uint32_t)arr * OFF_W + swz128((uint32_t)r, (uint32_t)g);
        CP_ASYNC16(dst, base + (size_t)r * 2048 + koff + (size_t)(g * 16));
    }
    CP_COMMIT();
}

// ---------------- fused GEMM layer: fp16 x fp16, fp32 accum, warp tile 64x32 ----------------
// MODE 0: relu(C+bias)->fp16 | MODE 1: C+bias+res->fp16 | MODE 2: C+bias+res->fp32
template<int MODE>
__global__ void __launch_bounds__(NTHREADS, 2)
k_gemm(const __half* __restrict__ X, const __half* __restrict__ W,
       const float* __restrict__ bias,
       __half* __restrict__ O,
       const __half* __restrict__ R,
       float* __restrict__ Of)
{
    extern __shared__ char smem[];
    const uint32_t sb = smem_u32(smem);
    const int tid = threadIdx.x, wid = tid >> 5, lane = tid & 31;
    const int Mb = blockIdx.y * BM, Nb = blockIdx.x * BN;
    const int wm = (wid & 1) * 64;          // 2 m-warps
    const int wn = (wid >> 1) * 32;         // 4 n-warps

    const char* pX = (const char*)(X + (size_t)Mb * DIM);
    const char* pW = (const char*)(W + (size_t)Nb * DIM);

    const int l7  = lane & 7;
    const int l15 = lane & 15;
    const int lhi = lane >> 4;              // 0/1
    const int lb8 = ((lane >> 3) & 1) << 3;

    // row-base addresses (swizzle col term added per kk)
    // NOTE: for every fragment row here, (row & 7) == l7, so the swizzled
    // column offset cx = ((2kk+lhi) ^ l7) << 4 is shared by ALL ldmatrix ops.
    uint32_t rbA[4], rbB[2], cx[4];
#pragma unroll
    for (int mi = 0; mi < 4; mi++) rbA[mi] = (uint32_t)((wm + mi * 16 + l15) * 128);
#pragma unroll
    for (int j = 0; j < 2; j++)  rbB[j]  = (uint32_t)((wn + j * 16 + l7 + lb8) * 128);
#pragma unroll
    for (int kk = 0; kk < 4; kk++)
        cx[kk] = ((uint32_t)(2 * kk + lhi) ^ (uint32_t)l7) << 4;

    float acc[4][4][4];
#pragma unroll
    for (int mi = 0; mi < 4; mi++)
#pragma unroll
        for (int ni = 0; ni < 4; ni++)
#pragma unroll
            for (int k = 0; k < 4; k++) acc[mi][ni][k] = 0.f;

    load_chunk(sb, 0, tid, pX, pW);

#pragma unroll 1
    for (int c = 0; c < NCHUNK; c++) {
        const uint32_t st = sb + (uint32_t)(c & 1) * STAGE;
        if (c + 1 < NCHUNK) {
            load_chunk(sb + (uint32_t)((c + 1) & 1) * STAGE, c + 1, tid, pX, pW);
            CP_WAIT1();
        } else {
            CP_WAIT0();
        }
        __syncthreads();

        const uint32_t stX = st, stW = st + OFF_W;
#pragma unroll
        for (int kk = 0; kk < 4; kk++) {
            uint32_t aF[4][4], bF[2][4];
#pragma unroll
            for (int mi = 0; mi < 4; mi++)
                LDSM_X4(aF[mi][0], aF[mi][1], aF[mi][2], aF[mi][3], stX + rbA[mi] + cx[kk]);
#pragma unroll
            for (int j = 0; j < 2; j++)
                LDSM_X4(bF[j][0], bF[j][1], bF[j][2], bF[j][3], stW + rbB[j] + cx[kk]);
#pragma unroll
            for (int mi = 0; mi < 4; mi++)
#pragma unroll
                for (int j = 0; j < 2; j++) {
                    MMA4(acc[mi][2 * j],     aF[mi][0], aF[mi][1], aF[mi][2], aF[mi][3], bF[j][0], bF[j][2]);
                    MMA4(acc[mi][2 * j + 1], aF[mi][0], aF[mi][1], aF[mi][2], aF[mi][3], bF[j][1], bF[j][3]);
                }
        }
        __syncthreads();
    }

    // ---- epilogue ----
    auto emit = [&](int r, int c, float v0, float v1) {
        size_t off = (size_t)r * DIM + c;
        if (MODE >= 1) {
            __half2 r2 = *reinterpret_cast<const __half2*>(R + off);
            v0 += __half2float(r2.x);
            v1 += __half2float(r2.y);
        }
        if (MODE == 0) { v0 = fmaxf(v0, 0.f); v1 = fmaxf(v1, 0.f); }
        if (MODE == 2) {
            *reinterpret_cast<float2*>(Of + off) = make_float2(v0, v1);
        } else {
            __half2 h2; h2.x = __float2half(v0); h2.y = __float2half(v1);
            *reinterpret_cast<__half2*>(O + off) = h2;
        }
    };

    const int g  = lane >> 2;
    const int tg = lane & 3;
#pragma unroll
    for (int mi = 0; mi < 4; mi++) {
#pragma unroll
        for (int ni = 0; ni < 4; ni++) {
            int r0 = Mb + wm + mi * 16 + g;
            int c0 = Nb + wn + ni * 8 + tg * 2;
            float b0 = __ldg(bias + c0), b1 = __ldg(bias + c0 + 1);
            emit(r0,     c0, acc[mi][ni][0] + b0, acc[mi][ni][1] + b1);
            emit(r0 + 8, c0, acc[mi][ni][2] + b0, acc[mi][ni][3] + b1);
        }
    }
}

// ---------------- split input x -> fp16 in R ----------------
__global__ void k_split(const float* __restrict__ x, __half* __restrict__ r) {
    int i4 = blockIdx.x * blockDim.x + threadIdx.x;
    float4 v = reinterpret_cast<const float4*>(x)[i4];
    __half2 h0; h0.x = __float2half(v.x); h0.y = __float2half(v.y);
    __half2 h1; h1.x = __float2half(v.z); h1.y = __float2half(v.w);
    __half2* R2 = reinterpret_cast<__half2*>(r);
    R2[i4 * 2]     = h0;
    R2[i4 * 2 + 1] = h1;
}

// ---------------- dequant + fold LoRA -> fp16 W (2 outputs/thread; R11 core) ----------------
__global__ void __launch_bounds__(256)
k_prep(const int* __restrict__ qw, const float* __restrict__ scale,
       const float* __restrict__ la, const float* __restrict__ lb) {
    int idx2 = blockIdx.x * 256 + threadIdx.x;        // < 18*1024*512
    int l    = idx2 >> 19;
    int rem  = idx2 & 0x7FFFF;
    int o    = rem >> 9;
    int i    = (rem & 511) * 2;

    size_t base = ((size_t)l << 20) + ((size_t)o << 10) + (size_t)i;
    int2 q2 = *reinterpret_cast<const int2*>(qw + base);
    float s = scale[(l << 16) + (o << 6) + (i >> 4)];
    float w0 = ((float)q2.x / 15.0f * 2.0f - 1.0f) * s;
    float w1 = ((float)q2.y / 15.0f * 2.0f - 1.0f) * s;

    const float4* lb4 = reinterpret_cast<const float4*>(lb + l * (DIM * 32) + o * 32);
    float lbv[32];
#pragma unroll
    for (int q = 0; q < 8; q++) {
        float4 v = lb4[q];
        lbv[q * 4]     = v.x; lbv[q * 4 + 1] = v.y;
        lbv[q * 4 + 2] = v.z; lbv[q * 4 + 3] = v.w;
    }

    const float* lar = la + l * (32 * DIM) + i;
    unsigned long long accp;
    PACK2(accp, w0, w1);
#pragma unroll
    for (int r = 0; r < 32; r++) {
        float2 a2 = *reinterpret_cast<const float2*>(lar + (size_t)r * DIM);
        unsigned long long ap, bp;
        PACK2(ap, a2.x, a2.y);
        PACK2(bp, lbv[r], lbv[r]);
        FMA2(accp, bp, ap);
    }
    float r0, r1;
    UNPACK2(r0, r1, accp);

    __half2 h2; h2.x = __float2half(r0); h2.y = __float2half(r1);
    *reinterpret_cast<__half2*>(g_W + base) = h2;
}

// ---------------- LayerNorm (fp16 in/out, vectorized) ----------------
__device__ __forceinline__ float blockSum256(float v, float* red) {
#pragma unroll
    for (int o = 16; o > 0; o >>= 1) v += __shfl_xor_sync(0xffffffffu, v, o);
    int w = threadIdx.x >> 5;
    if ((threadIdx.x & 31) == 0) red[w] = v;
    __syncthreads();
    float t = 0.f;
#pragma unroll
    for (int i = 0; i < 8; i++) t += red[i];
    __syncthreads();
    return t;
}

__global__ void k_ln(const __half* __restrict__ I,
                     const float* __restrict__ gw, const float* __restrict__ gb,
                     __half* __restrict__ O)
{
    __shared__ float red[8];
    const int row = blockIdx.x;
    const int tid = threadIdx.x;
    const size_t base = (size_t)row * DIM;
    const int c0 = tid * 4;

    uint2 iv = *reinterpret_cast<const uint2*>(I + base + c0);
    const __half2* ip = reinterpret_cast<const __half2*>(&iv);
    float x[4];
    x[0] = __half2float(ip[0].x);
    x[1] = __half2float(ip[0].y);
    x[2] = __half2float(ip[1].x);
    x[3] = __half2float(ip[1].y);

    float s = x[0] + x[1] + x[2] + x[3];
    float mu = blockSum256(s, red) * (1.0f / DIM);
    float d[4], s2 = 0.f;
#pragma unroll
    for (int j = 0; j < 4; j++) { d[j] = x[j] - mu; s2 += d[j] * d[j]; }
    float var = blockSum256(s2, red) * (1.0f / DIM);
    float inv = rsqrtf(var + 1e-5f);

    float4 gwv = *reinterpret_cast<const float4*>(gw + c0);
    float4 gbv = *reinterpret_cast<const float4*>(gb + c0);
    float y0 = d[0] * inv * gwv.x + gbv.x;
    float y1 = d[1] * inv * gwv.y + gbv.y;
    float y2 = d[2] * inv * gwv.z + gbv.z;
    float y3 = d[3] * inv * gwv.w + gbv.w;

    uint2 ov;
    __half2* op = reinterpret_cast<__half2*>(&ov);
    op[0].x = __float2half(y0); op[0].y = __float2half(y1);
    op[1].x = __float2half(y2); op[1].y = __float2half(y3);
    *reinterpret_cast<uint2*>(O + base + c0) = ov;
}

// ---------------- orchestration: 3-buffer rotation (R, A0, A1) ----------------
extern "C" void kernel_launch(void* const* d_in, const int* in_sizes, int n_in,
                              void* d_out, int out_size) {
    (void)in_sizes; (void)n_in; (void)out_size;
    const float* x     = (const float*)d_in[0];
    const float* scale = (const float*)d_in[1];
    const float* bias  = (const float*)d_in[2];
    const float* la    = (const float*)d_in[3];
    const float* lb    = (const float*)d_in[4];
    const float* lnw   = (const float*)d_in[5];
    const float* lnb   = (const float*)d_in[6];
    const int*   qw    = (const int*)d_in[7];

    __half *W, *A0, *A1, *R;
    cudaGetSymbolAddress((void**)&W,  g_W);
    cudaGetSymbolAddress((void**)&A0, g_A0);
    cudaGetSymbolAddress((void**)&A1, g_A1);
    cudaGetSymbolAddress((void**)&R,  g_R);

    cudaFuncSetAttribute(k_gemm<0>, cudaFuncAttributeMaxDynamicSharedMemorySize, SM_TOTAL);
    cudaFuncSetAttribute(k_gemm<1>, cudaFuncAttributeMaxDynamicSharedMemorySize, SM_TOTAL);
    cudaFuncSetAttribute(k_gemm<2>, cudaFuncAttributeMaxDynamicSharedMemorySize, SM_TOTAL);

    k_split<<<BATCH * DIM / 4 / 256, 256>>>(x, R);
    k_prep <<<NLAYERS * DIM * DIM / 2 / 256, 256>>>(qw, scale, la, lb);

    dim3 ggrid(DIM / BN, BATCH / BM);   // (8, 128)
    int li = 0;
    for (int blk = 0; blk < 6; ++blk) {
        // g0: R -> A0 (relu)
        const int W0 = li * DIM * DIM;
        k_gemm<0><<<ggrid, NTHREADS, SM_TOTAL>>>(R, W + W0, bias + li * DIM, A0, nullptr, nullptr);
        li++;
        // g1: A0 -> A1 (relu)
        const int W1 = li * DIM * DIM;
        k_gemm<0><<<ggrid, NTHREADS, SM_TOTAL>>>(A0, W + W1, bias + li * DIM, A1, nullptr, nullptr);
        li++;
        // g2: A1 + R(residual) -> A0  (or d_out for last block)
        const int W2 = li * DIM * DIM;
        if (blk < 5) {
            k_gemm<1><<<ggrid, NTHREADS, SM_TOTAL>>>(A1, W + W2, bias + li * DIM, A0, R, nullptr);
            li++;
            // LN: A0 -> R  (R doubles as next block's input AND residual)
            k_ln<<<BATCH, 256>>>(A0, lnw + blk * DIM, lnb + blk * DIM, R);
        } else {
            k_gemm<2><<<ggrid, NTHREADS, SM_TOTAL>>>(A1, W + W2, bias + li * DIM,
                                                     nullptr, R, (float*)d_out);
            li++;
        }
    }
}

// round 17
// speedup vs baseline: 1.8436x; 1.0109x over previous
#include <cuda_runtime.h>
#include <cuda_fp16.h>
#include <cstdint>

#define DIM     1024
#define BATCH   16384
#define NLAYERS 18

// ---------------- GEMM tiling: CTA 128x128, 8 warps, warp tile 64x32, BK=64 ----------------
#define BM 128
#define BN 128
#define BK 64                     // fp16 per K-chunk = 128B per row
#define NCHUNK (DIM / BK)         // 16
#define NTHREADS 256

// smem stage: X 128x128B = 16KB, W 128x128B = 16KB -> stage 32KB, 2 stages = 64KB/CTA
#define OFF_W  16384u
#define STAGE  32768u
#define SM_TOTAL (2 * 32768)

// ---------------- static device scratch ----------------
__device__ __align__(16) __half g_W  [NLAYERS * DIM * DIM];
__device__ __align__(16) __half g_lB [NLAYERS * DIM * 32];   // lb fp16 [l][o][r]
__device__ __align__(16) __half g_lAT[NLAYERS * DIM * 32];   // la fp16 transposed [l][i][r]
__device__ __align__(16) __half g_A0 [BATCH * DIM];
__device__ __align__(16) __half g_A1 [BATCH * DIM];
__device__ __align__(16) __half g_R  [BATCH * DIM];

// ---------------- PTX helpers ----------------
__device__ __forceinline__ uint32_t smem_u32(const void* p) {
    uint32_t a;
    asm("{ .reg .u64 t; cvta.to.shared.u64 t, %1; cvt.u32.u64 %0, t; }" : "=r"(a) : "l"(p));
    return a;
}
#define CP_ASYNC16(dst, src) \
    asm volatile("cp.async.cg.shared.global [%0], [%1], 16;\n" :: "r"(dst), "l"(src))
#define CP_COMMIT() asm volatile("cp.async.commit_group;\n" ::: "memory")
#define CP_WAIT1()  asm volatile("cp.async.wait_group 1;\n" ::: "memory")
#define CP_WAIT0()  asm volatile("cp.async.wait_group 0;\n" ::: "memory")

#define LDSM_X4(r0, r1, r2, r3, addr) \
    asm volatile("ldmatrix.sync.aligned.m8n8.x4.shared.b16 {%0,%1,%2,%3}, [%4];\n" \
                 : "=r"(r0), "=r"(r1), "=r"(r2), "=r"(r3) : "r"(addr))

#define MMA4(d, a0, a1, a2, a3, b0, b1) \
    asm volatile("mma.sync.aligned.m16n8k16.row.col.f32.f16.f16.f32 " \
                 "{%0,%1,%2,%3},{%4,%5,%6,%7},{%8,%9},{%0,%1,%2,%3};\n" \
                 : "+f"((d)[0]), "+f"((d)[1]), "+f"((d)[2]), "+f"((d)[3]) \
                 : "r"(a0), "r"(a1), "r"(a2), "r"(a3), "r"(b0), "r"(b1))

// swizzle for 128B rows: 16B-group g XOR (row & 7)  [k_gemm]
__device__ __forceinline__ uint32_t swz128(uint32_t row, uint32_t g16) {
    return row * 128u + ((g16 ^ (row & 7u)) << 4);
}
// swizzle for 64B rows: 16B-group g XOR (row & 3)  [k_ba, verified R6..R13]
__device__ __forceinline__ uint32_t swz64(uint32_t row, uint32_t g16) {
    return row * 64u + ((g16 ^ (row & 3u)) << 4);
}

// stage loader (k_gemm): 32KB / 256 threads = 8 cp.async x16B per thread
__device__ __forceinline__ void load_chunk(
    uint32_t st, int c, int tid, const char* pX, const char* pW)
{
    const size_t koff = (size_t)c * 128u;
#pragma unroll
    for (int i = 0; i < 8; i++) {
        int idx = tid + i * NTHREADS;     // 0..2047
        int arr = idx >> 10;              // 0: X, 1: W
        int r   = (idx >> 3) & 127;       // row 0..127
        int g   = idx & 7;                // 16B group 0..7
        const char* base = arr ? pW : pX;
        uint32_t dst = st + (uint32_t)arr * OFF_W + swz128((uint32_t)r, (uint32_t)g);
        CP_ASYNC16(dst, base + (size_t)r * 2048 + koff + (size_t)(g * 16));
    }
    CP_COMMIT();
}

// ---------------- fused GEMM layer (R16 exact): fp16 x fp16, fp32 accum ----------------
// MODE 0: relu(C+bias)->fp16 | MODE 1: C+bias+res->fp16 | MODE 2: C+bias+res->fp32
template<int MODE>
__global__ void __launch_bounds__(NTHREADS, 2)
k_gemm(const __half* __restrict__ X, const __half* __restrict__ W,
       const float* __restrict__ bias,
       __half* __restrict__ O,
       const __half* __restrict__ R,
       float* __restrict__ Of)
{
    extern __shared__ char smem[];
    const uint32_t sb = smem_u32(smem);
    const int tid = threadIdx.x, wid = tid >> 5, lane = tid & 31;
    const int Mb = blockIdx.y * BM, Nb = blockIdx.x * BN;
    const int wm = (wid & 1) * 64;          // 2 m-warps
    const int wn = (wid >> 1) * 32;         // 4 n-warps

    const char* pX = (const char*)(X + (size_t)Mb * DIM);
    const char* pW = (const char*)(W + (size_t)Nb * DIM);

    const int l7  = lane & 7;
    const int l15 = lane & 15;
    const int lhi = lane >> 4;              // 0/1
    const int lb8 = ((lane >> 3) & 1) << 3;

    uint32_t rbA[4], rbB[2], cx[4];
#pragma unroll
    for (int mi = 0; mi < 4; mi++) rbA[mi] = (uint32_t)((wm + mi * 16 + l15) * 128);
#pragma unroll
    for (int j = 0; j < 2; j++)  rbB[j]  = (uint32_t)((wn + j * 16 + l7 + lb8) * 128);
#pragma unroll
    for (int kk = 0; kk < 4; kk++)
        cx[kk] = ((uint32_t)(2 * kk + lhi) ^ (uint32_t)l7) << 4;

    float acc[4][4][4];
#pragma unroll
    for (int mi = 0; mi < 4; mi++)
#pragma unroll
        for (int ni = 0; ni < 4; ni++)
#pragma unroll
            for (int k = 0; k < 4; k++) acc[mi][ni][k] = 0.f;

    load_chunk(sb, 0, tid, pX, pW);

#pragma unroll 1
    for (int c = 0; c < NCHUNK; c++) {
        const uint32_t st = sb + (uint32_t)(c & 1) * STAGE;
        if (c + 1 < NCHUNK) {
            load_chunk(sb + (uint32_t)((c + 1) & 1) * STAGE, c + 1, tid, pX, pW);
            CP_WAIT1();
        } else {
            CP_WAIT0();
        }
        __syncthreads();

        const uint32_t stX = st, stW = st + OFF_W;
#pragma unroll
        for (int kk = 0; kk < 4; kk++) {
            uint32_t aF[4][4], bF[2][4];
#pragma unroll
            for (int mi = 0; mi < 4; mi++)
                LDSM_X4(aF[mi][0], aF[mi][1], aF[mi][2], aF[mi][3], stX + rbA[mi] + cx[kk]);
#pragma unroll
            for (int j = 0; j < 2; j++)
                LDSM_X4(bF[j][0], bF[j][1], bF[j][2], bF[j][3], stW + rbB[j] + cx[kk]);
#pragma unroll
            for (int mi = 0; mi < 4; mi++)
#pragma unroll
                for (int j = 0; j < 2; j++) {
                    MMA4(acc[mi][2 * j],     aF[mi][0], aF[mi][1], aF[mi][2], aF[mi][3], bF[j][0], bF[j][2]);
                    MMA4(acc[mi][2 * j + 1], aF[mi][0], aF[mi][1], aF[mi][2], aF[mi][3], bF[j][1], bF[j][3]);
                }
        }
        __syncthreads();
    }

    // ---- epilogue ----
    auto emit = [&](int r, int c, float v0, float v1) {
        size_t off = (size_t)r * DIM + c;
        if (MODE >= 1) {
            __half2 r2 = *reinterpret_cast<const __half2*>(R + off);
            v0 += __half2float(r2.x);
            v1 += __half2float(r2.y);
        }
        if (MODE == 0) { v0 = fmaxf(v0, 0.f); v1 = fmaxf(v1, 0.f); }
        if (MODE == 2) {
            *reinterpret_cast<float2*>(Of + off) = make_float2(v0, v1);
        } else {
            __half2 h2; h2.x = __float2half(v0); h2.y = __float2half(v1);
            *reinterpret_cast<__half2*>(O + off) = h2;
        }
    };

    const int g  = lane >> 2;
    const int tg = lane & 3;
#pragma unroll
    for (int mi = 0; mi < 4; mi++) {
#pragma unroll
        for (int ni = 0; ni < 4; ni++) {
            int r0 = Mb + wm + mi * 16 + g;
            int c0 = Nb + wn + ni * 8 + tg * 2;
            float b0 = __ldg(bias + c0), b1 = __ldg(bias + c0 + 1);
            emit(r0,     c0, acc[mi][ni][0] + b0, acc[mi][ni][1] + b1);
            emit(r0 + 8, c0, acc[mi][ni][2] + b0, acc[mi][ni][3] + b1);
        }
    }
}

// ---------------- convert LoRA factors to fp16 (lb direct, la transposed) ----------------
__global__ void k_prepAB(const float* __restrict__ la, const float* __restrict__ lb) {
    int idx = blockIdx.x * 256 + threadIdx.x;         // < 18*32*1024
    // lb: [l][o][r] -> same flat layout
    g_lB[idx] = __float2half(lb[idx]);
    // la: idx as [l][r][i] -> g_lAT[l][i][r]
    int l = idx >> 15, r = (idx >> 10) & 31, i = idx & 1023;
    g_lAT[(l << 15) + (i << 5) + r] = __float2half(la[idx]);
}

// ---------------- W = dequant(qw,scale) + lb@la via tensor cores ----------------
// A-operand = lb [o][r] k-major; B-operand = lAT [i][r] k-major. K=32, one stage.
__global__ void __launch_bounds__(256)
k_ba(const int* __restrict__ qw, const float* __restrict__ scale)
{
    __shared__ __align__(128) char smem[16384];       // lb tile 8KB | lAT tile 8KB
    const uint32_t sb = smem_u32(smem);
    const int tid = threadIdx.x, wid = tid >> 5, lane = tid & 31;
    const int l  = blockIdx.z;
    const int Mb = blockIdx.y * 128;                  // o block
    const int Nb = blockIdx.x * 128;                  // i block
    const int wm = (wid & 1) * 64;
    const int wn = (wid >> 1) * 32;

    // stage: 1024 slots of 16B (2 arrays x 128 rows x 4 groups)
    const char* pB = (const char*)(g_lB  + ((size_t)l << 15) + ((size_t)Mb << 5));
    const char* pA = (const char*)(g_lAT + ((size_t)l << 15) + ((size_t)Nb << 5));
#pragma unroll
    for (int i = 0; i < 4; i++) {
        int idx = tid + i * 256;          // 0..1023
        int arr = idx >> 9;               // 0: lb, 1: lAT
        int r   = (idx >> 2) & 127;
        int g   = idx & 3;
        const char* base = arr ? pA : pB;
        uint32_t dst = sb + (uint32_t)arr * 8192u + swz64((uint32_t)r, (uint32_t)g);
        CP_ASYNC16(dst, base + (size_t)r * 64 + (size_t)(g * 16));
    }
    CP_COMMIT();
    CP_WAIT0();
    __syncthreads();

    const int l7  = lane & 7;
    const int l15 = lane & 15;
    const int lhi = lane >> 4;
    const int lb8 = ((lane >> 3) & 1) << 3;
    const int g   = lane >> 2;
    const int tg  = lane & 3;

    float acc[4][4][4];
#pragma unroll
    for (int mi = 0; mi < 4; mi++)
#pragma unroll
        for (int ni = 0; ni < 4; ni++)
#pragma unroll
            for (int k = 0; k < 4; k++) acc[mi][ni][k] = 0.f;

#pragma unroll
    for (int kk = 0; kk < 2; kk++) {
        uint32_t aF[4][4], bF[2][4];
#pragma unroll
        for (int mi = 0; mi < 4; mi++)
            LDSM_X4(aF[mi][0], aF[mi][1], aF[mi][2], aF[mi][3],
                    sb + swz64((uint32_t)(wm + mi * 16 + l15), (uint32_t)(2 * kk + lhi)));
#pragma unroll
        for (int j = 0; j < 2; j++)
            LDSM_X4(bF[j][0], bF[j][1], bF[j][2], bF[j][3],
                    sb + 8192u + swz64((uint32_t)(wn + j * 16 + l7 + lb8), (uint32_t)(2 * kk + lhi)));
#pragma unroll
        for (int mi = 0; mi < 4; mi++)
#pragma unroll
            for (int j = 0; j < 2; j++) {
                MMA4(acc[mi][2 * j],     aF[mi][0], aF[mi][1], aF[mi][2], aF[mi][3], bF[j][0], bF[j][2]);
                MMA4(acc[mi][2 * j + 1], aF[mi][0], aF[mi][1], aF[mi][2], aF[mi][3], bF[j][1], bF[j][3]);
            }
    }

    // epilogue: W[o][i] = (q/15*2-1)*s + acc
    auto emitw = [&](int o, int ii, float t0, float t1) {
        size_t base = ((size_t)l << 20) + ((size_t)o << 10) + (size_t)ii;
        int2 q2 = *reinterpret_cast<const int2*>(qw + base);
        float s = __ldg(scale + ((l << 16) + (o << 6) + (ii >> 4)));
        float w0 = ((float)q2.x / 15.0f * 2.0f - 1.0f) * s + t0;
        float w1 = ((float)q2.y / 15.0f * 2.0f - 1.0f) * s + t1;
        __half2 h2; h2.x = __float2half(w0); h2.y = __float2half(w1);
        *reinterpret_cast<__half2*>(g_W + base) = h2;
    };
#pragma unroll
    for (int mi = 0; mi < 4; mi++) {
#pragma unroll
        for (int ni = 0; ni < 4; ni++) {
            int o0 = Mb + wm + mi * 16 + g;
            int c0 = Nb + wn + ni * 8 + tg * 2;
            emitw(o0,     c0, acc[mi][ni][0], acc[mi][ni][1]);
            emitw(o0 + 8, c0, acc[mi][ni][2], acc[mi][ni][3]);
        }
    }
}

// ---------------- split input x -> fp16 in R ----------------
__global__ void k_split(const float* __restrict__ x, __half* __restrict__ r) {
    int i4 = blockIdx.x * blockDim.x + threadIdx.x;
    float4 v = reinterpret_cast<const float4*>(x)[i4];
    __half2 h0; h0.x = __float2half(v.x); h0.y = __float2half(v.y);
    __half2 h1; h1.x = __float2half(v.z); h1.y = __float2half(v.w);
    __half2* R2 = reinterpret_cast<__half2*>(r);
    R2[i4 * 2]     = h0;
    R2[i4 * 2 + 1] = h1;
}

// ---------------- LayerNorm (fp16 in/out, vectorized) ----------------
__device__ __forceinline__ float blockSum256(float v, float* red) {
#pragma unroll
    for (int o = 16; o > 0; o >>= 1) v += __shfl_xor_sync(0xffffffffu, v, o);
    int w = threadIdx.x >> 5;
    if ((threadIdx.x & 31) == 0) red[w] = v;
    __syncthreads();
    float t = 0.f;
#pragma unroll
    for (int i = 0; i < 8; i++) t += red[i];
    __syncthreads();
    return t;
}

__global__ void k_ln(const __half* __restrict__ I,
                     const float* __restrict__ gw, const float* __restrict__ gb,
                     __half* __restrict__ O)
{
    __shared__ float red[8];
    const int row = blockIdx.x;
    const int tid = threadIdx.x;
    const size_t base = (size_t)row * DIM;
    const int c0 = tid * 4;

    uint2 iv = *reinterpret_cast<const uint2*>(I + base + c0);
    const __half2* ip = reinterpret_cast<const __half2*>(&iv);
    float x[4];
    x[0] = __half2float(ip[0].x);
    x[1] = __half2float(ip[0].y);
    x[2] = __half2float(ip[1].x);
    x[3] = __half2float(ip[1].y);

    float s = x[0] + x[1] + x[2] + x[3];
    float mu = blockSum256(s, red) * (1.0f / DIM);
    float d[4], s2 = 0.f;
#pragma unroll
    for (int j = 0; j < 4; j++) { d[j] = x[j] - mu; s2 += d[j] * d[j]; }
    float var = blockSum256(s2, red) * (1.0f / DIM);
    float inv = rsqrtf(var + 1e-5f);

    float4 gwv = *reinterpret_cast<const float4*>(gw + c0);
    float4 gbv = *reinterpret_cast<const float4*>(gb + c0);
    float y0 = d[0] * inv * gwv.x + gbv.x;
    float y1 = d[1] * inv * gwv.y + gbv.y;
    float y2 = d[2] * inv * gwv.z + gbv.z;
    float y3 = d[3] * inv * gwv.w + gbv.w;

    uint2 ov;
    __half2* op = reinterpret_cast<__half2*>(&ov);
    op[0].x = __float2half(y0); op[0].y = __float2half(y1);
    op[1].x = __float2half(y2); op[1].y = __float2half(y3);
    *reinterpret_cast<uint2*>(O + base + c0) = ov;
}

// ---------------- orchestration: 3-buffer rotation (R, A0, A1) ----------------
extern "C" void kernel_launch(void* const* d_in, const int* in_sizes, int n_in,
                              void* d_out, int out_size) {
    (void)in_sizes; (void)n_in; (void)out_size;
    const float* x     = (const float*)d_in[0];
    const float* scale = (const float*)d_in[1];
    const float* bias  = (const float*)d_in[2];
    const float* la    = (const float*)d_in[3];
    const float* lb    = (const float*)d_in[4];
    const float* lnw   = (const float*)d_in[5];
    const float* lnb   = (const float*)d_in[6];
    const int*   qw    = (const int*)d_in[7];

    __half *W, *A0, *A1, *R;
    cudaGetSymbolAddress((void**)&W,  g_W);
    cudaGetSymbolAddress((void**)&A0, g_A0);
    cudaGetSymbolAddress((void**)&A1, g_A1);
    cudaGetSymbolAddress((void**)&R,  g_R);

    cudaFuncSetAttribute(k_gemm<0>, cudaFuncAttributeMaxDynamicSharedMemorySize, SM_TOTAL);
    cudaFuncSetAttribute(k_gemm<1>, cudaFuncAttributeMaxDynamicSharedMemorySize, SM_TOTAL);
    cudaFuncSetAttribute(k_gemm<2>, cudaFuncAttributeMaxDynamicSharedMemorySize, SM_TOTAL);

    k_split<<<BATCH * DIM / 4 / 256, 256>>>(x, R);
    k_prepAB<<<NLAYERS * 32 * DIM / 256, 256>>>(la, lb);
    {
        dim3 bgrid(DIM / 128, DIM / 128, NLAYERS);   // (8, 8, 18)
        k_ba<<<bgrid, 256>>>(qw, scale);
    }

    dim3 ggrid(DIM / BN, BATCH / BM);   // (8, 128)
    int li = 0;
    for (int blk = 0; blk < 6; ++blk) {
        // g0: R -> A0 (relu)
        const int W0 = li * DIM * DIM;
        k_gemm<0><<<ggrid, NTHREADS, SM_TOTAL>>>(R, W + W0, bias + li * DIM, A0, nullptr, nullptr);
        li++;
        // g1: A0 -> A1 (relu)
        const int W1 = li * DIM * DIM;
        k_gemm<0><<<ggrid, NTHREADS, SM_TOTAL>>>(A0, W + W1, bias + li * DIM, A1, nullptr, nullptr);
        li++;
        // g2: A1 + R(residual) -> A0  (or d_out for last block)
        const int W2 = li * DIM * DIM;
        if (blk < 5) {
            k_gemm<1><<<ggrid, NTHREADS, SM_TOTAL>>>(A1, W + W2, bias + li * DIM, A0, R, nullptr);
            li++;
            // LN: A0 -> R  (R doubles as next block's input AND residual)
            k_ln<<<BATCH, 256>>>(A0, lnw + blk * DIM, lnb + blk * DIM, R);
        } else {
            k_gemm<2><<<ggrid, NTHREADS, SM_TOTAL>>>(A1, W + W2, bias + li * DIM,
                                                     nullptr, R, (float*)d_out);
            li++;
        }
    }
}